// round 6
// baseline (speedup 1.0000x reference)
#include <cuda_runtime.h>
#include <cstdint>
#include <cstddef>

// Adaptive separable convolution (SepConv), sm_103a.
// out[b,c,y,w] = sum_i sum_j inp[b,c,y+i,w+j] * V[b,i,y,w] * Hz[b,j,y,w]
//
// Round-6 design:
//  * FFMA2 (fma.rn.f32x2, rt_SMSP=2 confirmed R2-R5) packed math, 4 adjacent
//    output pixels per thread, one channel per CTA, TILE 128x4, 128-thr CTAs.
//  * 4 weight phases of 7 tap-pairs (w[4][7] = 56 live regs) -> ~115 regs
//    -> 4 CTAs/SM (16 warps, ~25% occ) via __launch_bounds__(128, 4).
//  * #pragma unroll 2 on the i-loop: freed registers let ptxas interleave
//    iteration i+1's LDS/V loads with iteration i's FFMA2s (latency hiding).
//  * Rolling clamped V prefetch.

#define KF   51
#define BB   2
#define CC   3
#define HH   256
#define WW   256
#define HW   (HH * WW)            // 65536
#define IN_H (HH + KF - 1)        // 306
#define IN_W (WW + KF - 1)        // 306

#define TILE_W 128
#define TILE_H 4
#define PATCH_H (TILE_H + KF - 1) // 54
#define PATCH_W (TILE_W + KF - 1) // 178
#define PATCH_WP 180              // padded row: 720B; cols 178,179 zeroed
#define ROW_BYTES (PATCH_WP * 4)  // 720

#define NTHREADS 128              // 4 warps, one output row each
#define NPAIR_PH 7                // tap-pairs per phase
#define NPHASES  4                // 4*7 = 28 pairs (m = 0..27; m=27 is pad)

__device__ __forceinline__ uint64_t pk2(float lo, float hi) {
    uint64_t r;
    asm("mov.b64 %0, {%1,%2};" : "=l"(r) : "f"(lo), "f"(hi));
    return r;
}
__device__ __forceinline__ void ffma2(uint64_t& acc, uint64_t a, uint64_t b) {
    asm("fma.rn.f32x2 %0, %1, %2, %0;" : "+l"(acc) : "l"(a), "l"(b));
}
__device__ __forceinline__ float hadd2(uint64_t p) {
    float lo, hi;
    asm("mov.b64 {%0,%1}, %2;" : "=f"(lo), "=f"(hi) : "l"(p));
    return lo + hi;
}
__device__ __forceinline__ void lds64(uint64_t& q, uint32_t saddr) {
    asm("ld.shared.b64 %0, [%1];" : "=l"(q) : "r"(saddr));
}
__device__ __forceinline__ void lds128(uint64_t& q0, uint64_t& q1, uint32_t saddr) {
    asm("ld.shared.v2.u64 {%0,%1}, [%2];" : "=l"(q0), "=l"(q1) : "r"(saddr));
}

__global__ void __launch_bounds__(NTHREADS, 4)
sepconv_kernel(const float* __restrict__ inp,
               const float* __restrict__ ver,
               const float* __restrict__ hor,
               float* __restrict__ out)
{
    __shared__ __align__(16) float sm[PATCH_H][PATCH_WP];

    const int bx = blockIdx.x;            // 0..1   tile col
    const int by = blockIdx.y;            // 0..63  tile row
    const int bc = blockIdx.z;            // 0..5   (b, c) fused
    const int b  = bc / CC;
    const int c  = bc - b * CC;
    const int x0 = bx * TILE_W;
    const int y0 = by * TILE_H;

    const int tid  = threadIdx.x;
    const int lane = tid & 31;
    const int wy   = tid >> 5;            // warp id == row within tile
    const int y    = y0 + wy;             // output row
    const int w0   = x0 + 4 * lane;       // first of 4 output cols

    const float* Hb = hor + ((size_t)b * KF * HW) + (size_t)y * WW + w0;
    const float* Vb = ver + ((size_t)b * KF * HW) + (size_t)y * WW + w0;

    // ---- single patch fill for this CTA's channel (+ zero pad cols) ----
    {
        const float* src = inp + ((size_t)(b * CC + c) * IN_H + y0) * IN_W + x0;
        for (int t = tid; t < PATCH_H * (PATCH_W / 2); t += NTHREADS) {
            int r  = t / (PATCH_W / 2);
            int c2 = t - r * (PATCH_W / 2);
            float2 v = *(const float2*)(src + (size_t)r * IN_W + 2 * c2);
            *(float2*)(&sm[r][2 * c2]) = v;
        }
        if (tid < PATCH_H) {              // zero floats 178,179 of every row
            sm[tid][PATCH_W]     = 0.0f;
            sm[tid][PATCH_W + 1] = 0.0f;
        }
    }
    __syncthreads();

    // per-thread shared base address: row wy (+i), float col 4*lane
    const uint32_t smbase = (uint32_t)__cvta_generic_to_shared(&sm[0][0])
                          + (uint32_t)(wy * ROW_BYTES) + (uint32_t)(lane * 16);

    float res0 = 0.0f, res1 = 0.0f, res2 = 0.0f, res3 = 0.0f;

    // ================= 4 phases of 7 tap-pairs (compile-time) ===============
#pragma unroll
    for (int ph = 0; ph < NPHASES; ++ph) {
        // packed weights: w[p][r] = (Hz[j0], Hz[j0+1]) with j0 = 2m - p,
        // m = 7*ph + r. Out-of-range taps -> 0 (compile-time predication).
        uint64_t w[4][NPAIR_PH];
#pragma unroll
        for (int p = 0; p < 4; ++p) {
#pragma unroll
            for (int r = 0; r < NPAIR_PH; ++r) {
                int m  = NPAIR_PH * ph + r;
                int j0 = 2 * m - p;
                int j1 = j0 + 1;
                float f0 = (j0 >= 0 && j0 < KF) ? Hb[(size_t)j0 * HW + p] : 0.0f;
                float f1 = (j1 >= 0 && j1 < KF) ? Hb[(size_t)j1 * HW + p] : 0.0f;
                w[p][r] = pk2(f0, f1);
            }
        }

        uint64_t o0 = 0, o1 = 0, o2 = 0, o3 = 0;
        // byte offset of pair m=7ph relative to lane base: 8*m
        const uint32_t sphase = smbase + (uint32_t)(8 * NPAIR_PH * ph);

        float4 v4 = *(const float4*)Vb;   // prologue V load (i = 0)

#pragma unroll 2
        for (int i = 0; i < KF; ++i) {
            // rolling clamped V prefetch for i+1
            const float* Vn = Vb + (size_t)((i + 1 < KF) ? (i + 1) : i) * HW;
            float4 vnext = *(const float4*)Vn;

            const uint32_t srow = sphase + (uint32_t)i * ROW_BYTES;

            // load the 7 q-pairs for this phase (16B-aligned pairs combined)
            uint64_t q[NPAIR_PH];
#pragma unroll
            for (int r = 0; r < NPAIR_PH; ) {
                int m = NPAIR_PH * ph + r;
                if ((m & 1) == 0 && r + 1 < NPAIR_PH) {
                    lds128(q[r], q[r + 1], srow + 8u * r);
                    r += 2;
                } else {
                    lds64(q[r], srow + 8u * r);
                    r += 1;
                }
            }

            uint64_t a0 = 0, a1 = 0, a2 = 0, a3 = 0;
#pragma unroll
            for (int r = 0; r < NPAIR_PH; ++r) {
                ffma2(a0, w[0][r], q[r]);
                ffma2(a1, w[1][r], q[r]);
                ffma2(a2, w[2][r], q[r]);
                ffma2(a3, w[3][r], q[r]);
            }
            ffma2(o0, pk2(v4.x, v4.x), a0);
            ffma2(o1, pk2(v4.y, v4.y), a1);
            ffma2(o2, pk2(v4.z, v4.z), a2);
            ffma2(o3, pk2(v4.w, v4.w), a3);
            v4 = vnext;
        }
        res0 += hadd2(o0);
        res1 += hadd2(o1);
        res2 += hadd2(o2);
        res3 += hadd2(o3);
    }

    // ---- write out ----
    float* o = out + ((size_t)(b * CC + c) * HH + y) * WW + w0;
    *(float4*)o = make_float4(res0, res1, res2, res3);
}

extern "C" void kernel_launch(void* const* d_in, const int* in_sizes, int n_in,
                              void* d_out, int out_size)
{
    (void)in_sizes; (void)n_in; (void)out_size;
    const float* inp = (const float*)d_in[0];   // [B, C, 306, 306]
    const float* ver = (const float*)d_in[1];   // [B, 51, 256, 256]
    const float* hor = (const float*)d_in[2];   // [B, 51, 256, 256]
    float*       out = (float*)d_out;           // [B, C, 256, 256]

    dim3 grid(WW / TILE_W, HH / TILE_H, BB * CC);   // (2, 64, 6) = 768 blocks
    dim3 block(NTHREADS);
    sepconv_kernel<<<grid, block>>>(inp, ver, hor, out);
}

// round 7
// speedup vs baseline: 2.1161x; 2.1161x over previous
#include <cuda_runtime.h>
#include <cstdint>
#include <cstddef>

// Adaptive separable convolution (SepConv), sm_103a.
// out[b,c,y,w] = sum_i sum_j inp[b,c,y+i,w+j] * V[b,i,y,w] * Hz[b,j,y,w]
//
// Round-7 = Round-6 design with the spill bug fixed:
//  * phase loop is "#pragma unroll 1" with RUNTIME ph -> ONE 56-reg weight set
//    physically reused across the 4 phases (R6's full unroll kept all 4 sets
//    live -> ptxas spilled weights to local -> 205us; L2=44% signature).
//  * FFMA2 (fma.rn.f32x2) packed math, 4 adjacent output pixels per thread,
//    one channel per CTA, TILE 128x4, 128-thread CTAs, 4 CTAs/SM.
//  * "#pragma unroll 2" on the i-loop for cross-iteration latency hiding.
//  * all shared loads are ld.shared.b64 (8B-aligned for any runtime phase).

#define KF   51
#define BB   2
#define CC   3
#define HH   256
#define WW   256
#define HW   (HH * WW)            // 65536
#define IN_H (HH + KF - 1)        // 306
#define IN_W (WW + KF - 1)        // 306

#define TILE_W 128
#define TILE_H 4
#define PATCH_H (TILE_H + KF - 1) // 54
#define PATCH_W (TILE_W + KF - 1) // 178
#define PATCH_WP 180              // padded row: 720B; cols 178,179 zeroed
#define ROW_BYTES (PATCH_WP * 4)  // 720

#define NTHREADS 128              // 4 warps, one output row each
#define NPAIR_PH 7                // tap-pairs per phase
#define NPHASES  4                // 4*7 = 28 pairs (m = 0..27; m=27 all-pad)

__device__ __forceinline__ uint64_t pk2(float lo, float hi) {
    uint64_t r;
    asm("mov.b64 %0, {%1,%2};" : "=l"(r) : "f"(lo), "f"(hi));
    return r;
}
__device__ __forceinline__ void ffma2(uint64_t& acc, uint64_t a, uint64_t b) {
    asm("fma.rn.f32x2 %0, %1, %2, %0;" : "+l"(acc) : "l"(a), "l"(b));
}
__device__ __forceinline__ float hadd2(uint64_t p) {
    float lo, hi;
    asm("mov.b64 {%0,%1}, %2;" : "=f"(lo), "=f"(hi) : "l"(p));
    return lo + hi;
}
__device__ __forceinline__ void lds64(uint64_t& q, uint32_t saddr) {
    asm("ld.shared.b64 %0, [%1];" : "=l"(q) : "r"(saddr));
}

__global__ void __launch_bounds__(NTHREADS, 4)
sepconv_kernel(const float* __restrict__ inp,
               const float* __restrict__ ver,
               const float* __restrict__ hor,
               float* __restrict__ out)
{
    __shared__ __align__(16) float sm[PATCH_H][PATCH_WP];

    const int bx = blockIdx.x;            // 0..1   tile col
    const int by = blockIdx.y;            // 0..63  tile row
    const int bc = blockIdx.z;            // 0..5   (b, c) fused
    const int b  = bc / CC;
    const int c  = bc - b * CC;
    const int x0 = bx * TILE_W;
    const int y0 = by * TILE_H;

    const int tid  = threadIdx.x;
    const int lane = tid & 31;
    const int wy   = tid >> 5;            // warp id == row within tile
    const int y    = y0 + wy;             // output row
    const int w0   = x0 + 4 * lane;       // first of 4 output cols

    const float* Hb = hor + ((size_t)b * KF * HW) + (size_t)y * WW + w0;
    const float* Vb = ver + ((size_t)b * KF * HW) + (size_t)y * WW + w0;

    // ---- single patch fill for this CTA's channel (+ zero pad cols) ----
    {
        const float* src = inp + ((size_t)(b * CC + c) * IN_H + y0) * IN_W + x0;
        for (int t = tid; t < PATCH_H * (PATCH_W / 2); t += NTHREADS) {
            int r  = t / (PATCH_W / 2);
            int c2 = t - r * (PATCH_W / 2);
            float2 v = *(const float2*)(src + (size_t)r * IN_W + 2 * c2);
            *(float2*)(&sm[r][2 * c2]) = v;
        }
        if (tid < PATCH_H) {              // zero floats 178,179 of every row
            sm[tid][PATCH_W]     = 0.0f;
            sm[tid][PATCH_W + 1] = 0.0f;
        }
    }
    __syncthreads();

    // per-thread shared base address: row wy (+i), float col 4*lane
    const uint32_t smbase = (uint32_t)__cvta_generic_to_shared(&sm[0][0])
                          + (uint32_t)(wy * ROW_BYTES) + (uint32_t)(lane * 16);

    float res0 = 0.0f, res1 = 0.0f, res2 = 0.0f, res3 = 0.0f;

    // ============ 4 phases of 7 tap-pairs, RUNTIME ph (regs reused) =========
#pragma unroll 1
    for (int ph = 0; ph < NPHASES; ++ph) {
        const int mbase = NPAIR_PH * ph;

        // packed weights: w[p][r] = (Hz[j0], Hz[j0+1]), j0 = 2(mbase+r) - p.
        // Out-of-range taps contribute 0 (predicated loads).
        uint64_t w[4][NPAIR_PH];
#pragma unroll
        for (int p = 0; p < 4; ++p) {
            const float* Hp = Hb + p;
#pragma unroll
            for (int r = 0; r < NPAIR_PH; ++r) {
                int j0 = 2 * (mbase + r) - p;
                int j1 = j0 + 1;
                float f0 = (j0 >= 0 && j0 < KF) ? Hp[(size_t)j0 * HW] : 0.0f;
                float f1 = (j1 >= 0 && j1 < KF) ? Hp[(size_t)j1 * HW] : 0.0f;
                w[p][r] = pk2(f0, f1);
            }
        }

        uint64_t o0 = 0, o1 = 0, o2 = 0, o3 = 0;
        // byte offset of pair mbase relative to lane base: 8*mbase
        uint32_t srow = smbase + (uint32_t)(8 * mbase);

        float4 v4 = *(const float4*)Vb;   // prologue V load (i = 0)

#pragma unroll 2
        for (int i = 0; i < KF; ++i) {
            // rolling clamped V prefetch for i+1
            const float* Vn = Vb + (size_t)((i + 1 < KF) ? (i + 1) : i) * HW;
            float4 vnext = *(const float4*)Vn;

            uint64_t q[NPAIR_PH];
#pragma unroll
            for (int r = 0; r < NPAIR_PH; ++r)
                lds64(q[r], srow + 8u * r);
            srow += ROW_BYTES;

            uint64_t a0 = 0, a1 = 0, a2 = 0, a3 = 0;
#pragma unroll
            for (int r = 0; r < NPAIR_PH; ++r) {
                ffma2(a0, w[0][r], q[r]);
                ffma2(a1, w[1][r], q[r]);
                ffma2(a2, w[2][r], q[r]);
                ffma2(a3, w[3][r], q[r]);
            }
            ffma2(o0, pk2(v4.x, v4.x), a0);
            ffma2(o1, pk2(v4.y, v4.y), a1);
            ffma2(o2, pk2(v4.z, v4.z), a2);
            ffma2(o3, pk2(v4.w, v4.w), a3);
            v4 = vnext;
        }
        res0 += hadd2(o0);
        res1 += hadd2(o1);
        res2 += hadd2(o2);
        res3 += hadd2(o3);
    }

    // ---- write out ----
    float* o = out + ((size_t)(b * CC + c) * HH + y) * WW + w0;
    *(float4*)o = make_float4(res0, res1, res2, res3);
}

extern "C" void kernel_launch(void* const* d_in, const int* in_sizes, int n_in,
                              void* d_out, int out_size)
{
    (void)in_sizes; (void)n_in; (void)out_size;
    const float* inp = (const float*)d_in[0];   // [B, C, 306, 306]
    const float* ver = (const float*)d_in[1];   // [B, 51, 256, 256]
    const float* hor = (const float*)d_in[2];   // [B, 51, 256, 256]
    float*       out = (float*)d_out;           // [B, C, 256, 256]

    dim3 grid(WW / TILE_W, HH / TILE_H, BB * CC);   // (2, 64, 6) = 768 blocks
    dim3 block(NTHREADS);
    sepconv_kernel<<<grid, block>>>(inp, ver, hor, out);
}

// round 8
// speedup vs baseline: 2.8849x; 1.3633x over previous
#include <cuda_runtime.h>
#include <cstdint>
#include <cstddef>

// Adaptive separable convolution (SepConv), sm_103a.
// out[b,c,y,w] = sum_i sum_j inp[b,c,y+i,w+j] * V[b,i,y,w] * Hz[b,j,y,w]
//
// Round-8 = Round-3 (best, 70.6us) with ONE change: shared pairs are loaded
// directly via ld.shared.v2.u64 at the same dense 16B-aligned addresses the
// float4 loads used. Identical conflict-free crossbar pattern, but the 14
// pk2 MOVs per iteration disappear and LDS results feed FFMA2 directly
// (saves ~20% of the issue stream + one 4-cyc ALU hop on the LDS->FMA path).
//
//  * FFMA2 (fma.rn.f32x2) packed math, 4 adjacent output pixels per thread.
//  * One channel per CTA (grid z = B*C), TILE 128x4, 128-thread CTAs, 3 CTAs/SM.
//  * 2 weight phases (pairs m = 0..13 / 14..26), ~108 live weight regs each.

#define KF   51
#define BB   2
#define CC   3
#define HH   256
#define WW   256
#define HW   (HH * WW)            // 65536
#define IN_H (HH + KF - 1)        // 306
#define IN_W (WW + KF - 1)        // 306

#define TILE_W 128
#define TILE_H 4
#define PATCH_H (TILE_H + KF - 1) // 54
#define PATCH_W (TILE_W + KF - 1) // 178
#define PATCH_WP 180              // padded row: 720B, 16B-aligned
#define ROW_BYTES (PATCH_WP * 4)  // 720

#define NTHREADS 128              // 4 warps, one output row each

__device__ __forceinline__ uint64_t pk2(float lo, float hi) {
    uint64_t r;
    asm("mov.b64 %0, {%1,%2};" : "=l"(r) : "f"(lo), "f"(hi));
    return r;
}
__device__ __forceinline__ void ffma2(uint64_t& acc, uint64_t a, uint64_t b) {
    asm("fma.rn.f32x2 %0, %1, %2, %0;" : "+l"(acc) : "l"(a), "l"(b));
}
__device__ __forceinline__ float hadd2(uint64_t p) {
    float lo, hi;
    asm("mov.b64 {%0,%1}, %2;" : "=f"(lo), "=f"(hi) : "l"(p));
    return lo + hi;
}
__device__ __forceinline__ void lds128(uint64_t& q0, uint64_t& q1, uint32_t saddr) {
    asm("ld.shared.v2.u64 {%0,%1}, [%2];" : "=l"(q0), "=l"(q1) : "r"(saddr));
}
__device__ __forceinline__ void lds64(uint64_t& q, uint32_t saddr) {
    asm("ld.shared.b64 %0, [%1];" : "=l"(q) : "r"(saddr));
}

__global__ void __launch_bounds__(NTHREADS, 3)
sepconv_kernel(const float* __restrict__ inp,
               const float* __restrict__ ver,
               const float* __restrict__ hor,
               float* __restrict__ out)
{
    __shared__ __align__(16) float sm[PATCH_H][PATCH_WP];

    const int bx = blockIdx.x;            // 0..1   tile col
    const int by = blockIdx.y;            // 0..63  tile row
    const int bc = blockIdx.z;            // 0..5   (b, c) fused
    const int b  = bc / CC;
    const int c  = bc - b * CC;
    const int x0 = bx * TILE_W;
    const int y0 = by * TILE_H;

    const int tid  = threadIdx.x;
    const int lane = tid & 31;
    const int wy   = tid >> 5;            // warp id == row within tile
    const int y    = y0 + wy;             // output row
    const int w0   = x0 + 4 * lane;       // first of 4 output cols

    const float* Hb = hor + ((size_t)b * KF * HW) + (size_t)y * WW + w0;
    const float* Vb = ver + ((size_t)b * KF * HW) + (size_t)y * WW + w0;

    // horizontal weight fetch for pixel p, tap j (compile-time predicated pad)
    auto hz = [&](int p, int j) -> float {
        return (j >= 0 && j < KF) ? Hb[(size_t)j * HW + p] : 0.0f;
    };

    // ---- single patch fill for this CTA's channel ----
    {
        const float* src = inp + ((size_t)(b * CC + c) * IN_H + y0) * IN_W + x0;
        for (int t = tid; t < PATCH_H * (PATCH_W / 2); t += NTHREADS) {
            int r  = t / (PATCH_W / 2);
            int c2 = t - r * (PATCH_W / 2);
            float2 v = *(const float2*)(src + (size_t)r * IN_W + 2 * c2);
            *(float2*)(&sm[r][2 * c2]) = v;
        }
    }

    // per-thread shared base address: row wy (+i), float col 4*lane
    const uint32_t smbase = (uint32_t)__cvta_generic_to_shared(&sm[0][0])
                          + (uint32_t)(wy * ROW_BYTES) + (uint32_t)(lane * 16);

    float res0, res1, res2, res3;

    // ================= PHASE A : pairs m = 0..13 (taps j <= 28) =============
    {
        uint64_t wa0[14], wa1[14], wa2[13], wa3[13];
#pragma unroll
        for (int k = 0; k < 14; ++k) {
            wa0[k] = pk2(hz(0, 2 * k),     hz(0, 2 * k + 1));
            wa1[k] = pk2(hz(1, 2 * k - 1), hz(1, 2 * k));
        }
#pragma unroll
        for (int k = 1; k < 14; ++k) {
            wa2[k - 1] = pk2(hz(2, 2 * k - 2), hz(2, 2 * k - 1));
            wa3[k - 1] = pk2(hz(3, 2 * k - 3), hz(3, 2 * k - 2));
        }

        __syncthreads();   // patch visible before compute

        uint64_t o0 = 0, o1 = 0, o2 = 0, o3 = 0;
        const float* Vp = Vb;
        uint32_t srow = smbase;
#pragma unroll 1
        for (int i = 0; i < KF; ++i) {
            float4 v4 = *(const float4*)Vp;
            Vp += HW;

            uint64_t q[14];
#pragma unroll
            for (int t = 0; t < 7; ++t)
                lds128(q[2 * t], q[2 * t + 1], srow + 16u * t);
            srow += ROW_BYTES;

            uint64_t a0 = 0, a1 = 0, a2 = 0, a3 = 0;
#pragma unroll
            for (int t = 0; t < 7; ++t) {
                int k0 = 2 * t, k1 = 2 * t + 1;
                ffma2(a0, wa0[k0], q[k0]);
                ffma2(a1, wa1[k0], q[k0]);
                if (k0 >= 1) { ffma2(a2, wa2[k0 - 1], q[k0]); ffma2(a3, wa3[k0 - 1], q[k0]); }
                ffma2(a0, wa0[k1], q[k1]);
                ffma2(a1, wa1[k1], q[k1]);
                ffma2(a2, wa2[k1 - 1], q[k1]);
                ffma2(a3, wa3[k1 - 1], q[k1]);
            }
            ffma2(o0, pk2(v4.x, v4.x), a0);
            ffma2(o1, pk2(v4.y, v4.y), a1);
            ffma2(o2, pk2(v4.z, v4.z), a2);
            ffma2(o3, pk2(v4.w, v4.w), a3);
        }
        res0 = hadd2(o0);
        res1 = hadd2(o1);
        res2 = hadd2(o2);
        res3 = hadd2(o3);
    }

    __syncthreads();   // fence: keep phase-B weight loads below phase A

    // ================= PHASE B : pairs m = 14..26 (taps j >= 25) ============
    {
        uint64_t wb0[12], wb1[12], wb2[13], wb3[13];
#pragma unroll
        for (int k = 14; k < 26; ++k) {
            wb0[k - 14] = pk2(hz(0, 2 * k),     hz(0, 2 * k + 1)); // k=25 -> pad
            wb1[k - 14] = pk2(hz(1, 2 * k - 1), hz(1, 2 * k));
        }
#pragma unroll
        for (int k = 14; k < 27; ++k) {
            wb2[k - 14] = pk2(hz(2, 2 * k - 2), hz(2, 2 * k - 1)); // k=26 -> pad
            wb3[k - 14] = pk2(hz(3, 2 * k - 3), hz(3, 2 * k - 2));
        }

        uint64_t o0 = 0, o1 = 0, o2 = 0, o3 = 0;
        const float* Vp = Vb;
        uint32_t srow = smbase + 112u;    // float 28 (16B-aligned)
#pragma unroll 1
        for (int i = 0; i < KF; ++i) {
            float4 v4 = *(const float4*)Vp;
            Vp += HW;

            uint64_t q[13];
#pragma unroll
            for (int t = 0; t < 6; ++t)
                lds128(q[2 * t], q[2 * t + 1], srow + 16u * t);
            lds64(q[12], srow + 96u);     // pair m=26 (floats 52,53 rel. lane)
            srow += ROW_BYTES;

            uint64_t a0 = 0, a1 = 0, a2 = 0, a3 = 0;
#pragma unroll
            for (int r = 0; r < 12; ++r) {
                ffma2(a0, wb0[r], q[r]);
                ffma2(a1, wb1[r], q[r]);
                ffma2(a2, wb2[r], q[r]);
                ffma2(a3, wb3[r], q[r]);
            }
            // tail pair m = 26: pixels 2,3 only
            ffma2(a2, wb2[12], q[12]);
            ffma2(a3, wb3[12], q[12]);

            ffma2(o0, pk2(v4.x, v4.x), a0);
            ffma2(o1, pk2(v4.y, v4.y), a1);
            ffma2(o2, pk2(v4.z, v4.z), a2);
            ffma2(o3, pk2(v4.w, v4.w), a3);
        }
        res0 += hadd2(o0);
        res1 += hadd2(o1);
        res2 += hadd2(o2);
        res3 += hadd2(o3);
    }

    // ---- write out ----
    float* o = out + ((size_t)(b * CC + c) * HH + y) * WW + w0;
    *(float4*)o = make_float4(res0, res1, res2, res3);
}

extern "C" void kernel_launch(void* const* d_in, const int* in_sizes, int n_in,
                              void* d_out, int out_size)
{
    (void)in_sizes; (void)n_in; (void)out_size;
    const float* inp = (const float*)d_in[0];   // [B, C, 306, 306]
    const float* ver = (const float*)d_in[1];   // [B, 51, 256, 256]
    const float* hor = (const float*)d_in[2];   // [B, 51, 256, 256]
    float*       out = (float*)d_out;           // [B, C, 256, 256]

    dim3 grid(WW / TILE_W, HH / TILE_H, BB * CC);   // (2, 64, 6) = 768 blocks
    dim3 block(NTHREADS);
    sepconv_kernel<<<grid, block>>>(inp, ver, hor, out);
}